// round 3
// baseline (speedup 1.0000x reference)
#include <cuda_runtime.h>
#include <cuda_bf16.h>

// Wasserstein CT cost-matrix mean.
// Algebraic identity: mean(matrix) = 2(C-1)/C^2 * mean(|ct|).
// Per pixel, sum_{c,l} |1{t==l} - 1{q==c}| = 2(C-1) regardless of t,q.
// So only ct matters: result = 2(C-1)/(C^2*N) * sum(|ct|).
//
// Single fused kernel, 32 CTAs: block partials + last-block (warp0-only)
// final reduction. Deterministic: fixed partial slots, fixed-order tree,
// ticket counter reset by the last block for graph replay.

#define RED_BLOCKS 32
#define RED_THREADS 256
#define UNROLL 8

__device__ float g_partials[RED_BLOCKS];
__device__ unsigned int g_ticket;  // zero-init; reset by last block each call

__device__ __forceinline__ float warp_reduce_sum(float v) {
    #pragma unroll
    for (int off = 16; off > 0; off >>= 1)
        v += __shfl_xor_sync(0xFFFFFFFFu, v, off);
    return v;
}

__global__ void __launch_bounds__(RED_THREADS)
abs_mean_fused(const float* __restrict__ ct, int n, float scale,
               float* __restrict__ out) {
    __shared__ float s_warp[RED_THREADS / 32];
    __shared__ bool s_is_last;

    const int tid = threadIdx.x;
    const int gtid = blockIdx.x * RED_THREADS + tid;
    const int nthreads = RED_BLOCKS * RED_THREADS;   // 8192

    const int nv4 = n >> 2;
    const float4* __restrict__ ct4 = reinterpret_cast<const float4*>(ct);

    float acc = 0.0f;

    // Fast path: nv4 == nthreads * UNROLL (n = 512*512). All 8 loads issue
    // back-to-back (front-batched MLP=8), fully unrolled, no loop checks.
    if (nv4 == nthreads * UNROLL) {
        float4 v[UNROLL];
        #pragma unroll
        for (int u = 0; u < UNROLL; u++)
            v[u] = ct4[gtid + u * nthreads];
        #pragma unroll
        for (int u = 0; u < UNROLL; u++)
            acc += fabsf(v[u].x) + fabsf(v[u].y) + fabsf(v[u].z) + fabsf(v[u].w);
    } else {
        // Robust grid-stride path for other sizes.
        for (int i = gtid; i < nv4; i += nthreads) {
            float4 v = ct4[i];
            acc += fabsf(v.x) + fabsf(v.y) + fabsf(v.z) + fabsf(v.w);
        }
        if (gtid == 0) {
            for (int i = nv4 << 2; i < n; i++) acc += fabsf(ct[i]);
        }
    }

    // Block reduction.
    acc = warp_reduce_sum(acc);
    if ((tid & 31) == 0) s_warp[tid >> 5] = acc;
    __syncthreads();
    if (tid < 32) {
        float v = (tid < RED_THREADS / 32) ? s_warp[tid] : 0.0f;
        v = warp_reduce_sum(v);
        if (tid == 0) {
            g_partials[blockIdx.x] = v;
            __threadfence();
            unsigned int t = atomicAdd(&g_ticket, 1u);
            s_is_last = (t == (unsigned int)(RED_BLOCKS - 1));
        }
    }
    __syncthreads();

    // Last block, warp 0 only: 32 partials -> one warp reduce -> scalar out.
    if (s_is_last && tid < 32) {
        float v = g_partials[tid];
        v = warp_reduce_sum(v);
        if (tid == 0) {
            out[0] = v * scale;
            g_ticket = 0u;  // restore for next graph replay
        }
    }
}

extern "C" void kernel_launch(void* const* d_in, const int* in_sizes, int n_in,
                              void* d_out, int out_size) {
    // Inputs (metadata order): pred_stage1 [1,C,H,W] f32, ct [1,H,W] f32,
    // target [1,1,H,W] i64. Only ct is needed (see identity above).
    const float* ct = (const float*)d_in[1];
    const int n = in_sizes[1];                      // H*W
    const int C = (n > 0) ? (in_sizes[0] / n) : 1;  // class count from pred size

    const double scale_d = (2.0 * (double)(C - 1)) /
                           ((double)C * (double)C * (double)n);
    const float scale = (float)scale_d;

    abs_mean_fused<<<RED_BLOCKS, RED_THREADS>>>(ct, n, scale, (float*)d_out);
}

// round 4
// speedup vs baseline: 1.0821x; 1.0821x over previous
#include <cuda_runtime.h>
#include <cuda_bf16.h>

// Wasserstein CT cost-matrix mean.
// Algebraic identity: mean(matrix) = 2(C-1)/C^2 * mean(|ct|).
// Per pixel, sum_{c,l} |1{t==l} - 1{q==c}| = 2(C-1) regardless of t,q.
// So only ct matters: result = 2(C-1)/(C^2*N) * sum(|ct|).
//
// Single fused kernel, 128 CTAs (max SM spread, minimal per-block work):
// block partials -> acq_rel ticket -> last block warp0 final reduce.
// Deterministic: fixed partial slots, fixed-order tree, ticket reset by
// the last block so each graph replay starts identically.

#define RED_BLOCKS 128
#define RED_THREADS 256
#define UNROLL 2

__device__ float4 g_partials4[RED_BLOCKS / 4];   // viewed as float[RED_BLOCKS]
__device__ unsigned int g_ticket;                 // zero-init; reset each call

__device__ __forceinline__ float warp_reduce_sum(float v) {
    #pragma unroll
    for (int off = 16; off > 0; off >>= 1)
        v += __shfl_xor_sync(0xFFFFFFFFu, v, off);
    return v;
}

__global__ void __launch_bounds__(RED_THREADS)
abs_mean_fused(const float* __restrict__ ct, int n, float scale,
               float* __restrict__ out) {
    __shared__ float s_warp[RED_THREADS / 32];
    __shared__ bool s_is_last;

    const int tid = threadIdx.x;
    const int gtid = blockIdx.x * RED_THREADS + tid;
    const int nthreads = RED_BLOCKS * RED_THREADS;   // 32768

    const int nv4 = n >> 2;
    const float4* __restrict__ ct4 = reinterpret_cast<const float4*>(ct);

    float acc = 0.0f;

    // Fast path: n = 512*512 -> each thread exactly UNROLL=2 float4 loads,
    // front-batched (both issue before any consume).
    if (nv4 == nthreads * UNROLL) {
        float4 v0 = ct4[gtid];
        float4 v1 = ct4[gtid + nthreads];
        acc  = fabsf(v0.x) + fabsf(v0.y) + fabsf(v0.z) + fabsf(v0.w);
        acc += fabsf(v1.x) + fabsf(v1.y) + fabsf(v1.z) + fabsf(v1.w);
    } else {
        // Robust grid-stride path for other sizes.
        for (int i = gtid; i < nv4; i += nthreads) {
            float4 v = ct4[i];
            acc += fabsf(v.x) + fabsf(v.y) + fabsf(v.z) + fabsf(v.w);
        }
        if (gtid == 0) {
            for (int i = nv4 << 2; i < n; i++) acc += fabsf(ct[i]);
        }
    }

    // Block reduction.
    acc = warp_reduce_sum(acc);
    if ((tid & 31) == 0) s_warp[tid >> 5] = acc;
    __syncthreads();
    if (tid < 32) {
        float v = (tid < RED_THREADS / 32) ? s_warp[tid] : 0.0f;
        v = warp_reduce_sum(v);
        if (tid == 0) {
            reinterpret_cast<float*>(g_partials4)[blockIdx.x] = v;
            // acq_rel RMW: release orders the partial store above; the
            // winning (last) increment's acquire makes ALL partials visible.
            unsigned int t;
            asm volatile("atom.add.acq_rel.gpu.u32 %0, [%1], %2;"
                         : "=r"(t)
                         : "l"(&g_ticket), "r"(1u)
                         : "memory");
            s_is_last = (t == (unsigned int)(RED_BLOCKS - 1));
        }
    }
    __syncthreads();

    // Last block, warp 0 only: 128 partials as 32x float4 (one coalesced
    // 512B load), 3 adds per lane, one warp reduce, scalar store.
    if (s_is_last && tid < 32) {
        float4 p = g_partials4[tid];
        float v = (p.x + p.y) + (p.z + p.w);
        v = warp_reduce_sum(v);
        if (tid == 0) {
            out[0] = v * scale;
            g_ticket = 0u;  // restore for next graph replay
        }
    }
}

extern "C" void kernel_launch(void* const* d_in, const int* in_sizes, int n_in,
                              void* d_out, int out_size) {
    // Inputs (metadata order): pred_stage1 [1,C,H,W] f32, ct [1,H,W] f32,
    // target [1,1,H,W] i64. Only ct is needed (see identity above).
    const float* ct = (const float*)d_in[1];
    const int n = in_sizes[1];                      // H*W
    const int C = (n > 0) ? (in_sizes[0] / n) : 1;  // class count from pred size

    const double scale_d = (2.0 * (double)(C - 1)) /
                           ((double)C * (double)C * (double)n);
    const float scale = (float)scale_d;

    abs_mean_fused<<<RED_BLOCKS, RED_THREADS>>>(ct, n, scale, (float*)d_out);
}